// round 2
// baseline (speedup 1.0000x reference)
#include <cuda_runtime.h>
#include <math.h>

#define CCH 512
#define BB  32
#define HW  4096
#define BN_EPS 1e-5f

// Scratch for per-(b,c) spatial sums of x. Allocation-free per harness rules.
__device__ float g_xsum[BB * CCH];

// ---------------------------------------------------------------------------
// Kernel 1: sum x[b,c,:,:] over the 64x64 spatial map. One block per (b,c).
// 256 threads * 4 float4 = 4096 floats. Coalesced, MLP=4 per thread.
// ---------------------------------------------------------------------------
__global__ __launch_bounds__(256) void reduce_x_kernel(const float* __restrict__ x) {
    const int bc = blockIdx.x;
    const float4* p = reinterpret_cast<const float4*>(x) + (size_t)bc * (HW / 4);
    const int t = threadIdx.x;

    // 4 independent loads issued up front (memory-level parallelism)
    float4 a = p[t];
    float4 b = p[t + 256];
    float4 c = p[t + 512];
    float4 d = p[t + 768];

    float s = (a.x + a.y) + (a.z + a.w)
            + (b.x + b.y) + (b.z + b.w)
            + (c.x + c.y) + (c.z + c.w)
            + (d.x + d.y) + (d.z + d.w);

    // warp reduce
    #pragma unroll
    for (int off = 16; off > 0; off >>= 1)
        s += __shfl_xor_sync(0xffffffffu, s, off);

    __shared__ float ws[8];
    const int w = t >> 5, l = t & 31;
    if (l == 0) ws[w] = s;
    __syncthreads();
    if (t == 0) {
        float tot = 0.f;
        #pragma unroll
        for (int i = 0; i < 8; i++) tot += ws[i];
        g_xsum[bc] = tot;
    }
}

// ---------------------------------------------------------------------------
// Kernel 2: pooled[b,c] = (xsum + sum_ij pe[c,i,j]*A[i]*A[j]) / 4096
// then y[b,o] = dot(pooled[b,:], conv_w[o,:]) + bias, BN(eval), ReLU.
// One block per batch element, 512 threads (thread == channel / out-channel).
// A[i] = column sums of the half-pixel bilinear resize weight matrix (7->64);
// border normalization in jax collapses to edge clamping, so closed form is exact.
// ---------------------------------------------------------------------------
__global__ __launch_bounds__(512) void finalize_kernel(
    const float* __restrict__ pe,      // (512,7,7)
    const float* __restrict__ conv_w,  // (512,512) [o,c]
    const float* __restrict__ conv_b,  // (512)
    const float* __restrict__ gamma,
    const float* __restrict__ beta,
    const float* __restrict__ rmean,
    const float* __restrict__ rvar,
    float* __restrict__ out)           // (32,512)
{
    const int b = blockIdx.x;
    const int t = threadIdx.x;

    __shared__ float A[7];
    __shared__ float pooled[CCH];

    if (t == 0) {
        #pragma unroll
        for (int i = 0; i < 7; i++) A[i] = 0.f;
        for (int o = 0; o < 64; o++) {
            float s = (o + 0.5f) * (7.0f / 64.0f) - 0.5f;
            if (s <= 0.f) {
                A[0] += 1.f;
            } else if (s >= 6.f) {
                A[6] += 1.f;
            } else {
                int i0 = (int)floorf(s);
                float f = s - (float)i0;
                A[i0]     += 1.f - f;
                A[i0 + 1] += f;
            }
        }
    }
    __syncthreads();

    // pooled for channel t
    {
        const float* pc = pe + t * 49;
        float psum = 0.f;
        #pragma unroll
        for (int i = 0; i < 7; i++) {
            float rs = 0.f;
            #pragma unroll
            for (int j = 0; j < 7; j++) rs = fmaf(pc[i * 7 + j], A[j], rs);
            psum = fmaf(rs, A[i], psum);
        }
        pooled[t] = (g_xsum[b * CCH + t] + psum) * (1.0f / (float)HW);
    }
    __syncthreads();

    // output channel t: dense 512-dot + BN + ReLU
    {
        const float* wr = conv_w + t * CCH;
        float acc = 0.f;
        #pragma unroll 8
        for (int c = 0; c < CCH; c++) acc = fmaf(pooled[c], wr[c], acc);
        float y = acc + conv_b[t];
        y = gamma[t] * (y - rmean[t]) * rsqrtf(rvar[t] + BN_EPS) + beta[t];
        out[b * CCH + t] = fmaxf(y, 0.f);
    }
}

extern "C" void kernel_launch(void* const* d_in, const int* in_sizes, int n_in,
                              void* d_out, int out_size) {
    const float* x      = (const float*)d_in[0];
    const float* pe     = (const float*)d_in[1];
    const float* conv_w = (const float*)d_in[2];
    const float* conv_b = (const float*)d_in[3];
    const float* gamma  = (const float*)d_in[4];
    const float* beta   = (const float*)d_in[5];
    const float* rmean  = (const float*)d_in[6];
    const float* rvar   = (const float*)d_in[7];
    float* out = (float*)d_out;

    reduce_x_kernel<<<BB * CCH, 256>>>(x);
    finalize_kernel<<<BB, 512>>>(pe, conv_w, conv_b, gamma, beta, rmean, rvar, out);
}

// round 4
// speedup vs baseline: 3.9198x; 3.9198x over previous
#include <cuda_runtime.h>
#include <math.h>

#define CCH 512
#define BB  32
#define HW  4096
#define BN_EPS 1e-5f

// Per-(b,c) pooled values (already includes pos-embed term and /4096).
__device__ float g_pooled[BB * CCH];

// 49 bilinear pooling weights A[i]*A[j], computed host-side, passed by value.
struct PEW { float w[49]; };

// ---------------------------------------------------------------------------
// Kernel 1: pooled[b,c] = ( sum_{hw} x[b,c,:,:] + sum_k pe[c,k]*W[k] ) / 4096
// One block per (b,c). 256 threads * 4 float4 = 4096 floats, coalesced, MLP=4.
// Warp 0 folds in the 49-term positional contribution with parallel loads.
// ---------------------------------------------------------------------------
__global__ __launch_bounds__(256) void reduce_x_kernel(
    const float* __restrict__ x, const float* __restrict__ pe, PEW pw)
{
    const int bc = blockIdx.x;
    const float4* p = reinterpret_cast<const float4*>(x) + (size_t)bc * (HW / 4);
    const int t = threadIdx.x;

    float4 a = p[t];
    float4 b = p[t + 256];
    float4 c = p[t + 512];
    float4 d = p[t + 768];

    float s = (a.x + a.y) + (a.z + a.w)
            + (b.x + b.y) + (b.z + b.w)
            + (c.x + c.y) + (c.z + c.w)
            + (d.x + d.y) + (d.z + d.w);

    #pragma unroll
    for (int off = 16; off > 0; off >>= 1)
        s += __shfl_xor_sync(0xffffffffu, s, off);

    __shared__ float ws[8];
    const int w = t >> 5, l = t & 31;
    if (l == 0) ws[w] = s;
    __syncthreads();

    if (t < 32) {
        // combine the 8 warp partials + the 49 pe terms in one warp reduction
        const int cch = bc & (CCH - 1);
        const float* pc = pe + cch * 49;
        float v = (l < 8) ? ws[l] : 0.f;
        v = fmaf(pc[l], pw.w[l], v);                       // terms 0..31
        if (l < 17) v = fmaf(pc[l + 32], pw.w[l + 32], v); // terms 32..48
        #pragma unroll
        for (int off = 16; off > 0; off >>= 1)
            v += __shfl_xor_sync(0xffffffffu, v, off);
        if (l == 0) g_pooled[bc] = v * (1.0f / (float)HW);
    }
}

// ---------------------------------------------------------------------------
// Kernel 2: y[b,o] = ReLU(BN(dot(pooled[b,:], conv_w[o,:]) + bias))
// One WARP per output element: 2048 blocks x 256 threads (8 warps).
// blockIdx.x = b*64 + otile; warp w handles output o = otile*8 + w.
// ---------------------------------------------------------------------------
__global__ __launch_bounds__(256) void gemm_kernel(
    const float* __restrict__ conv_w,
    const float* __restrict__ conv_b,
    const float* __restrict__ gamma,
    const float* __restrict__ beta,
    const float* __restrict__ rmean,
    const float* __restrict__ rvar,
    float* __restrict__ out)
{
    const int b  = blockIdx.x >> 6;
    const int o0 = (blockIdx.x & 63) * 8;
    const int t  = threadIdx.x;

    __shared__ float sp[CCH];
    sp[t]       = g_pooled[b * CCH + t];
    sp[t + 256] = g_pooled[b * CCH + t + 256];
    __syncthreads();

    const int w = t >> 5, l = t & 31;
    const int o = o0 + w;
    const float* wr = conv_w + (size_t)o * CCH;

    float acc = 0.f;
    #pragma unroll
    for (int i = 0; i < 16; i++)
        acc = fmaf(sp[l + 32 * i], wr[l + 32 * i], acc);

    #pragma unroll
    for (int off = 16; off > 0; off >>= 1)
        acc += __shfl_xor_sync(0xffffffffu, acc, off);

    if (l == 0) {
        float y = acc + conv_b[o];
        y = gamma[o] * (y - rmean[o]) * rsqrtf(rvar[o] + BN_EPS) + beta[o];
        out[b * CCH + o] = fmaxf(y, 0.f);
    }
}

extern "C" void kernel_launch(void* const* d_in, const int* in_sizes, int n_in,
                              void* d_out, int out_size) {
    const float* x      = (const float*)d_in[0];
    const float* pe     = (const float*)d_in[1];
    const float* conv_w = (const float*)d_in[2];
    const float* conv_b = (const float*)d_in[3];
    const float* gamma  = (const float*)d_in[4];
    const float* beta   = (const float*)d_in[5];
    const float* rmean  = (const float*)d_in[6];
    const float* rvar   = (const float*)d_in[7];
    float* out = (float*)d_out;

    // Host-side: bilinear 7->64 (half-pixel centers) column sums A[7],
    // then outer-product weights W[i*7+j] = A[i]*A[j].
    float A[7] = {0, 0, 0, 0, 0, 0, 0};
    for (int o = 0; o < 64; o++) {
        float s = (o + 0.5f) * (7.0f / 64.0f) - 0.5f;
        if (s <= 0.f)       A[0] += 1.f;
        else if (s >= 6.f)  A[6] += 1.f;
        else {
            int i0 = (int)floorf(s);
            float f = s - (float)i0;
            A[i0]     += 1.f - f;
            A[i0 + 1] += f;
        }
    }
    PEW pw;
    for (int i = 0; i < 7; i++)
        for (int j = 0; j < 7; j++)
            pw.w[i * 7 + j] = A[i] * A[j];

    reduce_x_kernel<<<BB * CCH, 256>>>(x, pe, pw);
    gemm_kernel<<<BB * 64, 256>>>(conv_w, conv_b, gamma, beta, rmean, rvar, out);
}

// round 5
// speedup vs baseline: 3.9279x; 1.0021x over previous
#include <cuda_runtime.h>
#include <math.h>

#define CCH 512
#define BB  32
#define HW  4096
#define BN_EPS 1e-5f

// Per-(b,c) pooled values (already includes pos-embed term and /4096).
__device__ float g_pooled[BB * CCH];

// 49 bilinear pooling weights A[i]*A[j], computed host-side, passed by value.
struct PEW { float w[49]; };

// ---------------------------------------------------------------------------
// Kernel 1: pooled[b,c] = ( sum_{hw} x[b,c,:,:] + sum_k pe[c,k]*W[k] ) / 4096
// One block per (b,c). 256 threads * 4 float4 = 4096 floats, coalesced, MLP=4.
// Warp 0 folds in the 49-term positional contribution with parallel loads.
// At 86% of HBM spec — near roofline, unchanged this round.
// ---------------------------------------------------------------------------
__global__ __launch_bounds__(256) void reduce_x_kernel(
    const float* __restrict__ x, const float* __restrict__ pe, PEW pw)
{
    const int bc = blockIdx.x;
    const float4* p = reinterpret_cast<const float4*>(x) + (size_t)bc * (HW / 4);
    const int t = threadIdx.x;

    float4 a = p[t];
    float4 b = p[t + 256];
    float4 c = p[t + 512];
    float4 d = p[t + 768];

    float s = (a.x + a.y) + (a.z + a.w)
            + (b.x + b.y) + (b.z + b.w)
            + (c.x + c.y) + (c.z + c.w)
            + (d.x + d.y) + (d.z + d.w);

    #pragma unroll
    for (int off = 16; off > 0; off >>= 1)
        s += __shfl_xor_sync(0xffffffffu, s, off);

    __shared__ float ws[8];
    const int w = t >> 5, l = t & 31;
    if (l == 0) ws[w] = s;
    __syncthreads();

    if (t < 32) {
        const int cch = bc & (CCH - 1);
        const float* pc = pe + cch * 49;
        float v = (l < 8) ? ws[l] : 0.f;
        v = fmaf(pc[l], pw.w[l], v);                       // terms 0..31
        if (l < 17) v = fmaf(pc[l + 32], pw.w[l + 32], v); // terms 32..48
        #pragma unroll
        for (int off = 16; off > 0; off >>= 1)
            v += __shfl_xor_sync(0xffffffffu, v, off);
        if (l == 0) g_pooled[bc] = v * (1.0f / (float)HW);
    }
}

// ---------------------------------------------------------------------------
// Kernel 2 (v2): batch-amortized dense layer.
// Block = 8 outputs (one per warp) x 8 batches. Grid = 64 o-tiles x 4 b-groups.
// Each lane caches 16 conv_w values in registers and reuses them for all
// 8 batches (conv_w L2 traffic: 32MB -> 4MB; 128 FMA per 16 global loads).
// ---------------------------------------------------------------------------
__global__ __launch_bounds__(256) void gemm_kernel(
    const float* __restrict__ conv_w,
    const float* __restrict__ conv_b,
    const float* __restrict__ gamma,
    const float* __restrict__ beta,
    const float* __restrict__ rmean,
    const float* __restrict__ rvar,
    float* __restrict__ out)
{
    const int b0 = (blockIdx.x & 3) * 8;        // batch group: 8 batches
    const int o0 = (blockIdx.x >> 2) * 8;       // output tile: 8 outputs
    const int t  = threadIdx.x;
    const int w  = t >> 5, l = t & 31;
    const int o  = o0 + w;

    // Stage pooled rows for the 8 batches: 8*512 floats = 16KB smem.
    __shared__ float sp[8 * CCH];
    {
        const float4* src = reinterpret_cast<const float4*>(g_pooled + b0 * CCH);
        float4* dst = reinterpret_cast<float4*>(sp);
        #pragma unroll
        for (int i = 0; i < 4; i++)
            dst[t + 256 * i] = src[t + 256 * i];
    }

    // Cache this warp's conv_w row in registers (16 per lane, coalesced).
    const float* wr = conv_w + (size_t)o * CCH;
    float wreg[16];
    #pragma unroll
    for (int i = 0; i < 16; i++)
        wreg[i] = wr[l + 32 * i];

    __syncthreads();

    // 8 batch dot-products reusing the cached weights.
    float acc[8];
    #pragma unroll
    for (int b = 0; b < 8; b++) {
        const float* spb = sp + b * CCH;
        float a = 0.f;
        #pragma unroll
        for (int i = 0; i < 16; i++)
            a = fmaf(spb[l + 32 * i], wreg[i], a);
        acc[b] = a;
    }

    // Butterfly-reduce all 8 accumulators (independent -> pipelined shuffles).
    #pragma unroll
    for (int off = 16; off > 0; off >>= 1) {
        #pragma unroll
        for (int b = 0; b < 8; b++)
            acc[b] += __shfl_xor_sync(0xffffffffu, acc[b], off);
    }

    if (l == 0) {
        const float bias = conv_b[o];
        const float g = gamma[o], bt = beta[o], mu = rmean[o];
        const float inv = rsqrtf(rvar[o] + BN_EPS);
        #pragma unroll
        for (int b = 0; b < 8; b++) {
            float y = g * (acc[b] + bias - mu) * inv + bt;
            out[(b0 + b) * CCH + o] = fmaxf(y, 0.f);
        }
    }
}

extern "C" void kernel_launch(void* const* d_in, const int* in_sizes, int n_in,
                              void* d_out, int out_size) {
    const float* x      = (const float*)d_in[0];
    const float* pe     = (const float*)d_in[1];
    const float* conv_w = (const float*)d_in[2];
    const float* conv_b = (const float*)d_in[3];
    const float* gamma  = (const float*)d_in[4];
    const float* beta   = (const float*)d_in[5];
    const float* rmean  = (const float*)d_in[6];
    const float* rvar   = (const float*)d_in[7];
    float* out = (float*)d_out;

    // Host-side: bilinear 7->64 (half-pixel centers) column sums A[7],
    // then outer-product weights W[i*7+j] = A[i]*A[j].
    float A[7] = {0, 0, 0, 0, 0, 0, 0};
    for (int o = 0; o < 64; o++) {
        float s = (o + 0.5f) * (7.0f / 64.0f) - 0.5f;
        if (s <= 0.f)       A[0] += 1.f;
        else if (s >= 6.f)  A[6] += 1.f;
        else {
            int i0 = (int)floorf(s);
            float f = s - (float)i0;
            A[i0]     += 1.f - f;
            A[i0 + 1] += f;
        }
    }
    PEW pw;
    for (int i = 0; i < 7; i++)
        for (int j = 0; j < 7; j++)
            pw.w[i * 7 + j] = A[i] * A[j];

    reduce_x_kernel<<<BB * CCH, 256>>>(x, pe, pw);
    gemm_kernel<<<64 * 4, 256>>>(conv_w, conv_b, gamma, beta, rmean, rvar, out);
}